// round 1
// baseline (speedup 1.0000x reference)
#include <cuda_runtime.h>
#include <cstdint>

#define B_  2
#define L_  2048
#define D_  1024
#define S_  256
#define V_  32000
#define M_  (B_*L_)   /* 4096 tokens */
#define EPS_ 1e-6f

// ---- scratch (allocation-free: __device__ globals) ----
__device__ float g_u  [M_*D_];   // normalized SSM input  [4096,1024]
__device__ float g_ubr[M_*S_];   // uB real               [4096,256]
__device__ float g_ubi[M_*S_];   // uB imag
__device__ float g_xsr[M_*S_];   // scan state real
__device__ float g_xsi[M_*S_];   // scan state imag
__device__ float g_y  [M_*D_];   // pre-head activations  [4096,1024]

__inline__ __device__ float warpSum(float v) {
#pragma unroll
    for (int o = 16; o > 0; o >>= 1) v += __shfl_down_sync(0xffffffffu, v, o);
    return v;
}

// -------------------------------------------------------------------------
// Kernel 1: embedding lookup + RMSNorm(w1) + RMSNorm(w2). One block/token.
// -------------------------------------------------------------------------
__global__ void embed_norm_kernel(const int* __restrict__ ids,
                                  const float* __restrict__ emb,
                                  const float* __restrict__ w1,
                                  const float* __restrict__ w2,
                                  float* __restrict__ u) {
    int token = blockIdx.x;
    int t = threadIdx.x;              // 256 threads, 4 elems each
    int id = ids[token];
    const float* e = emb + (size_t)id * D_;

    float v[4];
    float ss = 0.f;
#pragma unroll
    for (int i = 0; i < 4; i++) { v[i] = e[t + 256 * i]; ss += v[i] * v[i]; }

    __shared__ float red[8];
    int lane = t & 31, wid = t >> 5;
    float w = warpSum(ss);
    if (lane == 0) red[wid] = w;
    __syncthreads();
    if (wid == 0) {
        float q = (lane < 8) ? red[lane] : 0.f;
        q = warpSum(q);
        if (lane == 0) red[0] = rsqrtf(q / (float)D_ + EPS_);
    }
    __syncthreads();
    float r1 = red[0];
    __syncthreads();

    float x[4];
    float ss2 = 0.f;
#pragma unroll
    for (int i = 0; i < 4; i++) {
        x[i] = v[i] * r1 * w1[t + 256 * i];
        ss2 += x[i] * x[i];
    }
    float w2s = warpSum(ss2);
    if (lane == 0) red[wid] = w2s;
    __syncthreads();
    if (wid == 0) {
        float q = (lane < 8) ? red[lane] : 0.f;
        q = warpSum(q);
        if (lane == 0) red[0] = rsqrtf(q / (float)D_ + EPS_);
    }
    __syncthreads();
    float r2 = red[0];

#pragma unroll
    for (int i = 0; i < 4; i++)
        u[(size_t)token * D_ + t + 256 * i] = x[i] * r2 * w2[t + 256 * i];
}

// -------------------------------------------------------------------------
// Kernel 2: complex linear recurrence  x[l] = A*x[l-1] + uB[l]
// (exactly the FFT causal conv with kernel A^t). 512 independent (b,s) scans.
// -------------------------------------------------------------------------
__global__ void scan_kernel(const float* __restrict__ Are,
                            const float* __restrict__ Aim,
                            const float* __restrict__ ubr,
                            const float* __restrict__ ubi,
                            float* __restrict__ xsr,
                            float* __restrict__ xsi) {
    int g = blockIdx.x * blockDim.x + threadIdx.x;   // 0..511
    if (g >= B_ * S_) return;
    int s = g % S_;
    int b = g / S_;
    float ar = Are[s], ai = Aim[s];
    float xr = 0.f, xi = 0.f;
    size_t base = (size_t)b * L_ * S_ + s;
    for (int l = 0; l < L_; l++) {
        size_t idx = base + (size_t)l * S_;
        float ur = ubr[idx], ui = ubi[idx];
        float nxr = fmaf(ar, xr, fmaf(-ai, xi, ur));
        float nxi = fmaf(ar, xi, fmaf(ai, xr, ui));
        xr = nxr; xi = nxi;
        xsr[idx] = xr; xsi[idx] = xi;
    }
}

// -------------------------------------------------------------------------
// Kernel 3: fp32 tiled GEMM. C[M,N] = alpha*A[M,K]@B[K,N] (+bias) (+=C).
// 128x128 block tile, BK=8, 256 threads, 8x8 micro-tile.
// Requires M%128==0, N%128==0, K%8==0 (true for all our shapes).
// -------------------------------------------------------------------------
__global__ __launch_bounds__(256)
void sgemm128(const float* __restrict__ A, const float* __restrict__ Bm,
              float* __restrict__ C, const float* __restrict__ bias,
              int M, int N, int K, float alpha, int accumulate) {
    const int BM = 128, BN = 128, BK = 8;
    __shared__ float As[BK][BM];
    __shared__ float Bs[BK][BN];

    int tid = threadIdx.x;
    int tx = tid & 15, ty = tid >> 4;
    int brow = blockIdx.y * BM, bcol = blockIdx.x * BN;

    float acc[8][8];
#pragma unroll
    for (int i = 0; i < 8; i++)
#pragma unroll
        for (int j = 0; j < 8; j++) acc[i][j] = 0.f;

    int a_row = tid >> 1, a_col = (tid & 1) * 4;     // 128 rows x 8 cols
    int b_row = tid >> 5, b_col = (tid & 31) * 4;    // 8 rows x 128 cols

    const float* Ap = A + (size_t)brow * K;
    const float* Bp = Bm + bcol;

    for (int k0 = 0; k0 < K; k0 += BK) {
        float4 av = *(const float4*)(Ap + (size_t)a_row * K + k0 + a_col);
        As[a_col + 0][a_row] = av.x;
        As[a_col + 1][a_row] = av.y;
        As[a_col + 2][a_row] = av.z;
        As[a_col + 3][a_row] = av.w;
        float4 bv = *(const float4*)(Bp + (size_t)(k0 + b_row) * N + b_col);
        *(float4*)&Bs[b_row][b_col] = bv;
        __syncthreads();

#pragma unroll
        for (int k = 0; k < BK; k++) {
            float ar[8], br[8];
            *(float4*)(ar)     = *(const float4*)&As[k][ty * 8];
            *(float4*)(ar + 4) = *(const float4*)&As[k][ty * 8 + 4];
            *(float4*)(br)     = *(const float4*)&Bs[k][tx * 8];
            *(float4*)(br + 4) = *(const float4*)&Bs[k][tx * 8 + 4];
#pragma unroll
            for (int i = 0; i < 8; i++)
#pragma unroll
                for (int j = 0; j < 8; j++)
                    acc[i][j] = fmaf(ar[i], br[j], acc[i][j]);
        }
        __syncthreads();
    }

#pragma unroll
    for (int i = 0; i < 8; i++) {
        size_t row = (size_t)(brow + ty * 8 + i);
        float* Crow = C + row * N + bcol + tx * 8;
        const float* bp = bias ? (bias + bcol + tx * 8) : nullptr;
#pragma unroll
        for (int j = 0; j < 8; j++) {
            float v = alpha * acc[i][j];
            if (bp) v += bp[j];
            if (accumulate) v += Crow[j];
            Crow[j] = v;
        }
    }
}

// -------------------------------------------------------------------------
extern "C" void kernel_launch(void* const* d_in, const int* in_sizes, int n_in,
                              void* d_out, int out_size) {
    const int*   ids = (const int*)  d_in[0];
    const float* emb = (const float*)d_in[1];
    const float* w1  = (const float*)d_in[2];
    const float* w2  = (const float*)d_in[3];
    const float* Are = (const float*)d_in[4];
    const float* Aim = (const float*)d_in[5];
    const float* Bre = (const float*)d_in[6];
    const float* Bim = (const float*)d_in[7];
    const float* Cre = (const float*)d_in[8];
    const float* Cim = (const float*)d_in[9];
    const float* Dp  = (const float*)d_in[10];
    const float* Hw  = (const float*)d_in[11];
    const float* Hb  = (const float*)d_in[12];
    float* out = (float*)d_out;

    float *u, *ubr, *ubi, *xsr, *xsi, *y;
    cudaGetSymbolAddress((void**)&u,   g_u);
    cudaGetSymbolAddress((void**)&ubr, g_ubr);
    cudaGetSymbolAddress((void**)&ubi, g_ubi);
    cudaGetSymbolAddress((void**)&xsr, g_xsr);
    cudaGetSymbolAddress((void**)&xsi, g_xsi);
    cudaGetSymbolAddress((void**)&y,   g_y);

    // 1) embed + double RMSNorm
    embed_norm_kernel<<<M_, 256>>>(ids, emb, w1, w2, u);

    // 2) uB = u @ B  (real and imag)
    sgemm128<<<dim3(S_ / 128, M_ / 128), 256>>>(u, Bre, ubr, nullptr,
                                                M_, S_, D_, 1.f, 0);
    sgemm128<<<dim3(S_ / 128, M_ / 128), 256>>>(u, Bim, ubi, nullptr,
                                                M_, S_, D_, 1.f, 0);

    // 3) complex scan over L
    scan_kernel<<<2, 256>>>(Are, Aim, ubr, ubi, xsr, xsi);

    // 4) y = Re(xs @ Cc) + D_p  = xsr@Cre - xsi@Cim + D_p
    sgemm128<<<dim3(D_ / 128, M_ / 128), 256>>>(xsr, Cre, y, Dp,
                                                M_, D_, S_, 1.f, 0);
    sgemm128<<<dim3(D_ / 128, M_ / 128), 256>>>(xsi, Cim, y, nullptr,
                                                M_, D_, S_, -1.f, 1);

    // 5) logits = y @ head_w + head_b
    sgemm128<<<dim3(V_ / 128, M_ / 128), 256>>>(y, Hw, out, Hb,
                                                M_, V_, D_, 1.f, 0);
}

// round 3
// speedup vs baseline: 3.9851x; 3.9851x over previous
#include <cuda_runtime.h>
#include <cuda_bf16.h>
#include <cstdint>

#define B_  2
#define L_  2048
#define D_  1024
#define S_  256
#define V_  32000
#define M_  (B_*L_)     /* 4096 */
#define S2_ (2*S_)      /* 512  */
#define EPS_ 1e-6f

#define CH_ 32
#define CL_ (L_/CH_)

// ---------------- scratch (__device__ globals; no allocs) ----------------
__device__ float g_u  [M_*D_];
__device__ float g_ubr[M_*S_];
__device__ float g_ubi[M_*S_];
__device__ float g_xc [M_*S2_];          // [xsr | xsi] per token, fp32
__device__ float g_endr[B_*CH_*S_];
__device__ float g_endi[B_*CH_*S_];
__device__ float g_incr[B_*CH_*S_];
__device__ float g_inci[B_*CH_*S_];
__device__ __align__(1024) __nv_bfloat16 g_xchi[M_*S2_];
__device__ __align__(1024) __nv_bfloat16 g_xclo[M_*S2_];
__device__ __align__(1024) __nv_bfloat16 g_cchi[S2_*D_];
__device__ __align__(1024) __nv_bfloat16 g_cclo[S2_*D_];
__device__ __align__(1024) __nv_bfloat16 g_whi[(size_t)D_*V_];
__device__ __align__(1024) __nv_bfloat16 g_wlo[(size_t)D_*V_];
__device__ __align__(1024) float g_G[(size_t)S2_*V_];
__device__ __align__(1024) __nv_bfloat16 g_Ghi[(size_t)S2_*V_];
__device__ __align__(1024) __nv_bfloat16 g_Glo[(size_t)S2_*V_];
__device__ float g_gb[V_];

// ---------------- PTX helpers (base sm_103 target only) ------------------
__device__ __forceinline__ uint32_t smem_to_u32(const void* p) {
    uint32_t a;
    asm("{ .reg .u64 t; cvta.to.shared.u64 t, %1; cvt.u32.u64 %0, t; }"
        : "=r"(a) : "l"(p));
    return a;
}
__device__ __forceinline__ void cp_async16(uint32_t dst, const void* src) {
    asm volatile("cp.async.cg.shared.global [%0], [%1], 16;"
                 :: "r"(dst), "l"(src) : "memory");
}
#define CP_COMMIT() asm volatile("cp.async.commit_group;" ::: "memory")
#define CP_WAIT(n)  asm volatile("cp.async.wait_group %0;" :: "n"(n) : "memory")

#define LDSM4(r0,r1,r2,r3,a) \
    asm volatile("ldmatrix.sync.aligned.m8n8.x4.shared.b16 {%0,%1,%2,%3}, [%4];" \
        : "=r"(r0), "=r"(r1), "=r"(r2), "=r"(r3) : "r"(a))
#define LDSM4T(r0,r1,r2,r3,a) \
    asm volatile("ldmatrix.sync.aligned.m8n8.x4.trans.shared.b16 {%0,%1,%2,%3}, [%4];" \
        : "=r"(r0), "=r"(r1), "=r"(r2), "=r"(r3) : "r"(a))

#define MMA_BF16(d, a0,a1,a2,a3, b0,b1) \
    asm volatile("mma.sync.aligned.m16n8k16.row.col.f32.bf16.bf16.f32 " \
        "{%0,%1,%2,%3}, {%4,%5,%6,%7}, {%8,%9}, {%0,%1,%2,%3};" \
        : "+f"((d)[0]), "+f"((d)[1]), "+f"((d)[2]), "+f"((d)[3]) \
        : "r"(a0), "r"(a1), "r"(a2), "r"(a3), "r"(b0), "r"(b1))

__inline__ __device__ float warpSum(float v) {
#pragma unroll
    for (int o = 16; o > 0; o >>= 1) v += __shfl_down_sync(0xffffffffu, v, o);
    return v;
}

// =========================================================================
// Kernel: embedding + double RMSNorm
// =========================================================================
__global__ void embed_norm_kernel(const int* __restrict__ ids,
                                  const float* __restrict__ emb,
                                  const float* __restrict__ w1,
                                  const float* __restrict__ w2,
                                  float* __restrict__ u) {
    int token = blockIdx.x;
    int t = threadIdx.x;
    int id = ids[token];
    const float* e = emb + (size_t)id * D_;

    float v[4]; float ss = 0.f;
#pragma unroll
    for (int i = 0; i < 4; i++) { v[i] = e[t + 256 * i]; ss += v[i] * v[i]; }

    __shared__ float red[8];
    int lane = t & 31, wid = t >> 5;
    float w = warpSum(ss);
    if (lane == 0) red[wid] = w;
    __syncthreads();
    if (wid == 0) {
        float q = (lane < 8) ? red[lane] : 0.f;
        q = warpSum(q);
        if (lane == 0) red[0] = rsqrtf(q / (float)D_ + EPS_);
    }
    __syncthreads();
    float r1 = red[0];
    __syncthreads();

    float x[4]; float ss2 = 0.f;
#pragma unroll
    for (int i = 0; i < 4; i++) {
        x[i] = v[i] * r1 * w1[t + 256 * i];
        ss2 += x[i] * x[i];
    }
    float w2s = warpSum(ss2);
    if (lane == 0) red[wid] = w2s;
    __syncthreads();
    if (wid == 0) {
        float q = (lane < 8) ? red[lane] : 0.f;
        q = warpSum(q);
        if (lane == 0) red[0] = rsqrtf(q / (float)D_ + EPS_);
    }
    __syncthreads();
    float r2 = red[0];
#pragma unroll
    for (int i = 0; i < 4; i++)
        u[(size_t)token * D_ + t + 256 * i] = x[i] * r2 * w2[t + 256 * i];
}

// =========================================================================
// Chunked parallel complex scan  ->  writes packed xc = [re | im], stride 512
// =========================================================================
__global__ void scan_local_kernel(const float* __restrict__ Are,
                                  const float* __restrict__ Aim,
                                  const float* __restrict__ ubr,
                                  const float* __restrict__ ubi,
                                  float* __restrict__ xc,
                                  float* __restrict__ endr,
                                  float* __restrict__ endi) {
    int t = blockIdx.x * blockDim.x + threadIdx.x;
    int s = t % S_;
    int c = (t / S_) % CH_;
    int b = t / (S_ * CH_);
    float ar = Are[s], ai = Aim[s];
    float xr = 0.f, xi = 0.f;
    int tok0 = b * L_ + c * CL_;
    size_t ub_base = (size_t)tok0 * S_ + s;
    size_t xc_base = (size_t)tok0 * S2_ + s;
    for (int j = 0; j < CL_; j++) {
        size_t ui = ub_base + (size_t)j * S_;
        float ur = ubr[ui], uim = ubi[ui];
        float nr = fmaf(ar, xr, fmaf(-ai, xi, ur));
        float ni = fmaf(ar, xi, fmaf(ai, xr, uim));
        xr = nr; xi = ni;
        size_t xo = xc_base + (size_t)j * S2_;
        xc[xo] = xr; xc[xo + S_] = xi;
    }
    endr[(b * CH_ + c) * S_ + s] = xr;
    endi[(b * CH_ + c) * S_ + s] = xi;
}

__global__ void scan_combine_kernel(const float* __restrict__ Are,
                                    const float* __restrict__ Aim,
                                    const float* __restrict__ endr,
                                    const float* __restrict__ endi,
                                    float* __restrict__ incr,
                                    float* __restrict__ inci) {
    int t = blockIdx.x * blockDim.x + threadIdx.x;
    if (t >= B_ * S_) return;
    int s = t % S_;
    int b = t / S_;
    float ar = Are[s], ai = Aim[s];
    float pr = 1.f, pi = 0.f;
    for (int j = 0; j < CL_; j++) {
        float nr = pr * ar - pi * ai;
        float ni = pr * ai + pi * ar;
        pr = nr; pi = ni;
    }
    float cr = 0.f, ci = 0.f;
    for (int c = 0; c < CH_; c++) {
        int idx = (b * CH_ + c) * S_ + s;
        incr[idx] = cr; inci[idx] = ci;
        float er = endr[idx], ei = endi[idx];
        float nr = fmaf(pr, cr, fmaf(-pi, ci, er));
        float ni = fmaf(pr, ci, fmaf(pi, cr, ei));
        cr = nr; ci = ni;
    }
}

__global__ void scan_fix_kernel(const float* __restrict__ Are,
                                const float* __restrict__ Aim,
                                const float* __restrict__ incr,
                                const float* __restrict__ inci,
                                float* __restrict__ xc) {
    int t = blockIdx.x * blockDim.x + threadIdx.x;
    int s = t % S_;
    int c = (t / S_) % CH_;
    int b = t / (S_ * CH_);
    if (c == 0) return;
    int cidx = (b * CH_ + c) * S_ + s;
    float x0r = incr[cidx], x0i = inci[cidx];
    float ar = Are[s], ai = Aim[s];
    float pr = ar, pi = ai;
    int tok0 = b * L_ + c * CL_;
    size_t base = (size_t)tok0 * S2_ + s;
    for (int j = 0; j < CL_; j++) {
        size_t xo = base + (size_t)j * S2_;
        xc[xo]      += pr * x0r - pi * x0i;
        xc[xo + S_] += pr * x0i + pi * x0r;
        float nr = pr * ar - pi * ai;
        float ni = pr * ai + pi * ar;
        pr = nr; pi = ni;
    }
}

// =========================================================================
// fp32 tiled GEMM (used for the small uB GEMMs only)
// =========================================================================
__global__ __launch_bounds__(256)
void sgemm128(const float* __restrict__ A, const float* __restrict__ Bm,
              float* __restrict__ C, int M, int N, int K) {
    const int BMt = 128, BNt = 128, BKt = 8;
    __shared__ float As[BKt][BMt];
    __shared__ float Bs[BKt][BNt];

    int tid = threadIdx.x;
    int tx = tid & 15, ty = tid >> 4;
    int brow = blockIdx.y * BMt, bcol = blockIdx.x * BNt;

    float acc[8][8];
#pragma unroll
    for (int i = 0; i < 8; i++)
#pragma unroll
        for (int j = 0; j < 8; j++) acc[i][j] = 0.f;

    int a_row = tid >> 1, a_col = (tid & 1) * 4;
    int b_row = tid >> 5, b_col = (tid & 31) * 4;
    const float* Ap = A + (size_t)brow * K;
    const float* Bp = Bm + bcol;

    for (int k0 = 0; k0 < K; k0 += BKt) {
        float4 av = *(const float4*)(Ap + (size_t)a_row * K + k0 + a_col);
        As[a_col + 0][a_row] = av.x;
        As[a_col + 1][a_row] = av.y;
        As[a_col + 2][a_row] = av.z;
        As[a_col + 3][a_row] = av.w;
        float4 bv = *(const float4*)(Bp + (size_t)(k0 + b_row) * N + b_col);
        *(float4*)&Bs[b_row][b_col] = bv;
        __syncthreads();
#pragma unroll
        for (int k = 0; k < BKt; k++) {
            float ar[8], br[8];
            *(float4*)(ar)     = *(const float4*)&As[k][ty * 8];
            *(float4*)(ar + 4) = *(const float4*)&As[k][ty * 8 + 4];
            *(float4*)(br)     = *(const float4*)&Bs[k][tx * 8];
            *(float4*)(br + 4) = *(const float4*)&Bs[k][tx * 8 + 4];
#pragma unroll
            for (int i = 0; i < 8; i++)
#pragma unroll
                for (int j = 0; j < 8; j++)
                    acc[i][j] = fmaf(ar[i], br[j], acc[i][j]);
        }
        __syncthreads();
    }
#pragma unroll
    for (int i = 0; i < 8; i++) {
        float* Crow = C + (size_t)(brow + ty * 8 + i) * N + bcol + tx * 8;
#pragma unroll
        for (int j = 0; j < 8; j++) Crow[j] = acc[i][j];
    }
}

// =========================================================================
// Elementwise converters
// =========================================================================
__global__ void split_kernel(const float* __restrict__ x,
                             __nv_bfloat16* __restrict__ hi,
                             __nv_bfloat16* __restrict__ lo, size_t n) {
    size_t i = (size_t)blockIdx.x * blockDim.x + threadIdx.x;
    if (i >= n) return;
    float v = x[i];
    __nv_bfloat16 h = __float2bfloat16(v);
    hi[i] = h;
    lo[i] = __float2bfloat16(v - __bfloat162float(h));
}

// Build Ccat = [Cre ; -Cim] ([512,1024]) split to bf16 hi/lo
__global__ void ccat_kernel(const float* __restrict__ Cre,
                            const float* __restrict__ Cim,
                            __nv_bfloat16* __restrict__ hi,
                            __nv_bfloat16* __restrict__ lo) {
    int i = blockIdx.x * blockDim.x + threadIdx.x;     // 512*1024
    int row = i >> 10;
    int d = i & 1023;
    float v = (row < S_) ? Cre[row * D_ + d] : -Cim[(row - S_) * D_ + d];
    __nv_bfloat16 h = __float2bfloat16(v);
    hi[i] = h;
    lo[i] = __float2bfloat16(v - __bfloat162float(h));
}

// Fused: split Hw [D,V] -> whi/wlo, and gb[v] = sum_d Dp[d]*Hw[d,v] + Hb[v]
__global__ void wsplit_bias_kernel(const float* __restrict__ Hw,
                                   const float* __restrict__ Dp,
                                   const float* __restrict__ Hb,
                                   __nv_bfloat16* __restrict__ whi,
                                   __nv_bfloat16* __restrict__ wlo,
                                   float* __restrict__ gb) {
    int v = blockIdx.x * blockDim.x + threadIdx.x;     // 32000
    if (v >= V_) return;
    float acc = 0.f;
    for (int d = 0; d < D_; d++) {
        size_t o = (size_t)d * V_ + v;
        float w = Hw[o];
        __nv_bfloat16 h = __float2bfloat16(w);
        whi[o] = h;
        wlo[o] = __float2bfloat16(w - __bfloat162float(h));
        acc = fmaf(Dp[d], w, acc);
    }
    gb[v] = acc + Hb[v];
}

// =========================================================================
// Split-bf16 HMMA GEMM:  C[M,N] = Ahi/lo[M,K] @ Bhi/lo[K,N] (+bias)
// 3-term: Ahi*Bhi + Alo*Bhi + Ahi*Blo.  CTA 128x128, BK=32, 8 warps (2x4).
// A row-major k-contig; B row-major n-contig (ldmatrix .trans).
// =========================================================================
#define GBM 128
#define GBN 128
#define GBK 32
#define A_STRIDE 80            /* (32+8) bf16 = 80B per A row */
#define B_STRIDE 272           /* (128+8) bf16 = 272B per B row */
#define A_SPLIT  (128*A_STRIDE)        /* 10240 */
#define B_OFF    (2*A_SPLIT)           /* 20480 */
#define B_SPLIT  (GBK*B_STRIDE)        /* 8704  */
#define STAGE_BYTES (B_OFF + 2*B_SPLIT)  /* 37888 */
#define GSMEM (2*STAGE_BYTES)            /* 75776 */

__global__ __launch_bounds__(256)
void mma_gemm(const __nv_bfloat16* __restrict__ Ahi,
              const __nv_bfloat16* __restrict__ Alo,
              const __nv_bfloat16* __restrict__ Bhi,
              const __nv_bfloat16* __restrict__ Blo,
              float* __restrict__ C,
              const float* __restrict__ bias,
              int Mdim, int Ndim, int Kdim) {
    extern __shared__ char smem[];
    uint32_t sbase = smem_to_u32(smem);
    const int tid = threadIdx.x;
    const int lane = tid & 31, wid = tid >> 5;
    const int wm = wid & 1, wn = wid >> 1;          // 2 x 4 warps
    const int brow = blockIdx.x * GBM;              // M-tile fastest -> L2 reuse of B
    const int bcol = blockIdx.y * GBN;
    const int lda = Kdim, ldb = Ndim;
    const int niter = Kdim / GBK;

    float acc[4][4][4];
#pragma unroll
    for (int i = 0; i < 4; i++)
#pragma unroll
        for (int j = 0; j < 4; j++)
#pragma unroll
            for (int k = 0; k < 4; k++) acc[i][j][k] = 0.f;

    auto load_stage = [&](int kt, int st) {
        const int k0 = kt * GBK;
        uint32_t sa = sbase + st * STAGE_BYTES;
#pragma unroll
        for (int i = 0; i < 2; i++) {                // A: 512 chunks/split
            int c = tid + i * 256;
            int r = c >> 2, ch = c & 3;
            uint32_t dst = sa + r * A_STRIDE + ch * 16;
            size_t src = (size_t)(brow + r) * lda + k0 + ch * 8;
            cp_async16(dst,            Ahi + src);
            cp_async16(dst + A_SPLIT,  Alo + src);
        }
#pragma unroll
        for (int i = 0; i < 2; i++) {                // B: 512 chunks/split
            int c = tid + i * 256;
            int r = c >> 4, ch = c & 15;
            uint32_t dst = sa + B_OFF + r * B_STRIDE + ch * 16;
            size_t src = (size_t)(k0 + r) * ldb + bcol + ch * 8;
            cp_async16(dst,            Bhi + src);
            cp_async16(dst + B_SPLIT,  Blo + src);
        }
    };

    load_stage(0, 0);
    CP_COMMIT();

    for (int kt = 0; kt < niter; kt++) {
        if (kt + 1 < niter) {
            load_stage(kt + 1, (kt + 1) & 1);
            CP_COMMIT();
            CP_WAIT(1);
        } else {
            CP_WAIT(0);
        }
        __syncthreads();

        uint32_t sa = sbase + (kt & 1) * STAGE_BYTES;
#pragma unroll
        for (int ks = 0; ks < 2; ks++) {
            uint32_t ah[4][4], al[4][4];
#pragma unroll
            for (int mf = 0; mf < 4; mf++) {
                uint32_t addr = sa + (wm * 64 + mf * 16 + (lane & 15)) * A_STRIDE
                              + ks * 32 + (lane >> 4) * 16;
                LDSM4(ah[mf][0], ah[mf][1], ah[mf][2], ah[mf][3], addr);
                LDSM4(al[mf][0], al[mf][1], al[mf][2], al[mf][3], addr + A_SPLIT);
            }
            uint32_t bh[4][2], bl[4][2];
#pragma unroll
            for (int g = 0; g < 2; g++) {
                uint32_t addr = sa + B_OFF + (ks * 16 + (lane & 15)) * B_STRIDE
                              + (wn * 32 + g * 16 + (lane >> 4) * 8) * 2;
                uint32_t r0, r1, r2, r3;
                LDSM4T(r0, r1, r2, r3, addr);
                bh[2 * g][0] = r0; bh[2 * g][1] = r1;
                bh[2 * g + 1][0] = r2; bh[2 * g + 1][1] = r3;
                LDSM4T(r0, r1, r2, r3, addr + B_SPLIT);
                bl[2 * g][0] = r0; bl[2 * g][1] = r1;
                bl[2 * g + 1][0] = r2; bl[2 * g + 1][1] = r3;
            }
#pragma unroll
            for (int mf = 0; mf < 4; mf++)
#pragma unroll
                for (int nf = 0; nf < 4; nf++) {
                    MMA_BF16(acc[mf][nf], ah[mf][0], ah[mf][1], ah[mf][2], ah[mf][3],
                             bh[nf][0], bh[nf][1]);
                    MMA_BF16(acc[mf][nf], al[mf][0], al[mf][1], al[mf][2], al[mf][3],
                             bh[nf][0], bh[nf][1]);
                    MMA_BF16(acc[mf][nf], ah[mf][0], ah[mf][1], ah[mf][2], ah[mf][3],
                             bl[nf][0], bl[nf][1]);
                }
        }
        __syncthreads();
    }

    // epilogue: direct STG of c-fragments (+optional bias)
#pragma unroll
    for (int mf = 0; mf < 4; mf++) {
        int r0 = brow + wm * 64 + mf * 16 + (lane >> 2);
#pragma unroll
        for (int nf = 0; nf < 4; nf++) {
            int c0 = bcol + wn * 32 + nf * 8 + (lane & 3) * 2;
            float b0 = 0.f, b1 = 0.f;
            if (bias) { b0 = __ldg(bias + c0); b1 = __ldg(bias + c0 + 1); }
            float2 v0 = make_float2(acc[mf][nf][0] + b0, acc[mf][nf][1] + b1);
            float2 v1 = make_float2(acc[mf][nf][2] + b0, acc[mf][nf][3] + b1);
            *(float2*)(C + (size_t)r0 * Ndim + c0)       = v0;
            *(float2*)(C + (size_t)(r0 + 8) * Ndim + c0) = v1;
        }
    }
}

// =========================================================================
extern "C" void kernel_launch(void* const* d_in, const int* in_sizes, int n_in,
                              void* d_out, int out_size) {
    const int*   ids = (const int*)  d_in[0];
    const float* emb = (const float*)d_in[1];
    const float* w1  = (const float*)d_in[2];
    const float* w2  = (const float*)d_in[3];
    const float* Are = (const float*)d_in[4];
    const float* Aim = (const float*)d_in[5];
    const float* Bre = (const float*)d_in[6];
    const float* Bim = (const float*)d_in[7];
    const float* Cre = (const float*)d_in[8];
    const float* Cim = (const float*)d_in[9];
    const float* Dp  = (const float*)d_in[10];
    const float* Hw  = (const float*)d_in[11];
    const float* Hb  = (const float*)d_in[12];
    float* out = (float*)d_out;

    float *u, *ubr, *ubi, *xc, *endr, *endi, *incr, *inci, *G, *gb;
    __nv_bfloat16 *xchi, *xclo, *cchi, *cclo, *whi, *wlo, *Ghi, *Glo;
    cudaGetSymbolAddress((void**)&u,    g_u);
    cudaGetSymbolAddress((void**)&ubr,  g_ubr);
    cudaGetSymbolAddress((void**)&ubi,  g_ubi);
    cudaGetSymbolAddress((void**)&xc,   g_xc);
    cudaGetSymbolAddress((void**)&endr, g_endr);
    cudaGetSymbolAddress((void**)&endi, g_endi);
    cudaGetSymbolAddress((void**)&incr, g_incr);
    cudaGetSymbolAddress((void**)&inci, g_inci);
    cudaGetSymbolAddress((void**)&xchi, g_xchi);
    cudaGetSymbolAddress((void**)&xclo, g_xclo);
    cudaGetSymbolAddress((void**)&cchi, g_cchi);
    cudaGetSymbolAddress((void**)&cclo, g_cclo);
    cudaGetSymbolAddress((void**)&whi,  g_whi);
    cudaGetSymbolAddress((void**)&wlo,  g_wlo);
    cudaGetSymbolAddress((void**)&G,    g_G);
    cudaGetSymbolAddress((void**)&Ghi,  g_Ghi);
    cudaGetSymbolAddress((void**)&Glo,  g_Glo);
    cudaGetSymbolAddress((void**)&gb,   g_gb);

    cudaFuncSetAttribute(mma_gemm,
                         cudaFuncAttributeMaxDynamicSharedMemorySize, GSMEM);

    // weight prep (independent chain)
    wsplit_bias_kernel<<<(V_ + 255) / 256, 256>>>(Hw, Dp, Hb, whi, wlo, gb);
    ccat_kernel<<<(S2_ * D_) / 256, 256>>>(Cre, Cim, cchi, cclo);

    // G = Ccat @ Hw   [512, 32000]
    mma_gemm<<<dim3(S2_ / GBM, V_ / GBN), 256, GSMEM>>>(
        cchi, cclo, whi, wlo, G, nullptr, S2_, V_, D_);
    split_kernel<<<((size_t)S2_ * V_ + 255) / 256, 256>>>(G, Ghi, Glo,
                                                          (size_t)S2_ * V_);

    // activations chain
    embed_norm_kernel<<<M_, 256>>>(ids, emb, w1, w2, u);
    sgemm128<<<dim3(S_ / 128, M_ / 128), 256>>>(u, Bre, ubr, M_, S_, D_);
    sgemm128<<<dim3(S_ / 128, M_ / 128), 256>>>(u, Bim, ubi, M_, S_, D_);
    scan_local_kernel<<<(B_ * CH_ * S_) / 256, 256>>>(Are, Aim, ubr, ubi,
                                                      xc, endr, endi);
    scan_combine_kernel<<<(B_ * S_ + 255) / 256, 256>>>(Are, Aim, endr, endi,
                                                        incr, inci);
    scan_fix_kernel<<<(B_ * CH_ * S_) / 256, 256>>>(Are, Aim, incr, inci, xc);
    split_kernel<<<((size_t)M_ * S2_ + 255) / 256, 256>>>(xc, xchi, xclo,
                                                          (size_t)M_ * S2_);

    // logits = xc @ G + gb   [4096, 32000]
    mma_gemm<<<dim3(M_ / GBM, V_ / GBN), 256, GSMEM>>>(
        xchi, xclo, Ghi, Glo, out, gb, M_, V_, S2_);
}

// round 4
// speedup vs baseline: 4.4656x; 1.1206x over previous
#include <cuda_runtime.h>
#include <cuda_bf16.h>
#include <cstdint>

#define B_  2
#define L_  2048
#define D_  1024
#define S_  256
#define V_  32000
#define M_  (B_*L_)     /* 4096 */
#define S2_ (2*S_)      /* 512  */
#define EPS_ 1e-6f

#define CH_ 32
#define CL_ (L_/CH_)

// ---------------- scratch (__device__ globals; no allocs) ----------------
__device__ __align__(16) float g_ub [M_*S2_];    // packed [ubr | ubi]
__device__ __align__(16) float g_xc [M_*S2_];    // packed [xsr | xsi]
__device__ float g_endr[B_*CH_*S_];
__device__ float g_endi[B_*CH_*S_];
__device__ float g_incr[B_*CH_*S_];
__device__ float g_inci[B_*CH_*S_];
__device__ __align__(1024) __nv_bfloat16 g_uhi[M_*D_];
__device__ __align__(1024) __nv_bfloat16 g_ulo[M_*D_];
__device__ __align__(1024) __nv_bfloat16 g_bchi[D_*S2_];
__device__ __align__(1024) __nv_bfloat16 g_bclo[D_*S2_];
__device__ __align__(1024) __nv_bfloat16 g_xchi[M_*S2_];
__device__ __align__(1024) __nv_bfloat16 g_xclo[M_*S2_];
__device__ __align__(1024) __nv_bfloat16 g_cchi[S2_*D_];
__device__ __align__(1024) __nv_bfloat16 g_cclo[S2_*D_];
__device__ __align__(1024) __nv_bfloat16 g_whi[(size_t)D_*V_];
__device__ __align__(1024) __nv_bfloat16 g_wlo[(size_t)D_*V_];
__device__ __align__(1024) __nv_bfloat16 g_Ghi[(size_t)S2_*V_];
__device__ __align__(1024) __nv_bfloat16 g_Glo[(size_t)S2_*V_];
__device__ float g_gb[V_];

// ---------------- PTX helpers ------------------
__device__ __forceinline__ uint32_t smem_to_u32(const void* p) {
    uint32_t a;
    asm("{ .reg .u64 t; cvta.to.shared.u64 t, %1; cvt.u32.u64 %0, t; }"
        : "=r"(a) : "l"(p));
    return a;
}
__device__ __forceinline__ void cp_async16(uint32_t dst, const void* src) {
    asm volatile("cp.async.cg.shared.global [%0], [%1], 16;"
                 :: "r"(dst), "l"(src) : "memory");
}
#define CP_COMMIT() asm volatile("cp.async.commit_group;" ::: "memory")
#define CP_WAIT(n)  asm volatile("cp.async.wait_group %0;" :: "n"(n) : "memory")

#define LDSM4(r0,r1,r2,r3,a) \
    asm volatile("ldmatrix.sync.aligned.m8n8.x4.shared.b16 {%0,%1,%2,%3}, [%4];" \
        : "=r"(r0), "=r"(r1), "=r"(r2), "=r"(r3) : "r"(a))
#define LDSM4T(r0,r1,r2,r3,a) \
    asm volatile("ldmatrix.sync.aligned.m8n8.x4.trans.shared.b16 {%0,%1,%2,%3}, [%4];" \
        : "=r"(r0), "=r"(r1), "=r"(r2), "=r"(r3) : "r"(a))

#define MMA_BF16(d, a0,a1,a2,a3, b0,b1) \
    asm volatile("mma.sync.aligned.m16n8k16.row.col.f32.bf16.bf16.f32 " \
        "{%0,%1,%2,%3}, {%4,%5,%6,%7}, {%8,%9}, {%0,%1,%2,%3};" \
        : "+f"((d)[0]), "+f"((d)[1]), "+f"((d)[2]), "+f"((d)[3]) \
        : "r"(a0), "r"(a1), "r"(a2), "r"(a3), "r"(b0), "r"(b1))

__inline__ __device__ float warpSum(float v) {
#pragma unroll
    for (int o = 16; o > 0; o >>= 1) v += __shfl_down_sync(0xffffffffu, v, o);
    return v;
}

// =========================================================================
// embedding + double RMSNorm -> bf16 hi/lo
// =========================================================================
__global__ void embed_norm_kernel(const int* __restrict__ ids,
                                  const float* __restrict__ emb,
                                  const float* __restrict__ w1,
                                  const float* __restrict__ w2,
                                  __nv_bfloat16* __restrict__ uhi,
                                  __nv_bfloat16* __restrict__ ulo) {
    int token = blockIdx.x;
    int t = threadIdx.x;
    int id = ids[token];
    const float* e = emb + (size_t)id * D_;

    float v[4]; float ss = 0.f;
#pragma unroll
    for (int i = 0; i < 4; i++) { v[i] = e[t + 256 * i]; ss += v[i] * v[i]; }

    __shared__ float red[8];
    int lane = t & 31, wid = t >> 5;
    float w = warpSum(ss);
    if (lane == 0) red[wid] = w;
    __syncthreads();
    if (wid == 0) {
        float q = (lane < 8) ? red[lane] : 0.f;
        q = warpSum(q);
        if (lane == 0) red[0] = rsqrtf(q / (float)D_ + EPS_);
    }
    __syncthreads();
    float r1 = red[0];
    __syncthreads();

    float x[4]; float ss2 = 0.f;
#pragma unroll
    for (int i = 0; i < 4; i++) {
        x[i] = v[i] * r1 * w1[t + 256 * i];
        ss2 += x[i] * x[i];
    }
    float w2s = warpSum(ss2);
    if (lane == 0) red[wid] = w2s;
    __syncthreads();
    if (wid == 0) {
        float q = (lane < 8) ? red[lane] : 0.f;
        q = warpSum(q);
        if (lane == 0) red[0] = rsqrtf(q / (float)D_ + EPS_);
    }
    __syncthreads();
    float r2 = red[0];
#pragma unroll
    for (int i = 0; i < 4; i++) {
        float val = x[i] * r2 * w2[t + 256 * i];
        size_t o = (size_t)token * D_ + t + 256 * i;
        __nv_bfloat16 h = __float2bfloat16(val);
        uhi[o] = h;
        ulo[o] = __float2bfloat16(val - __bfloat162float(h));
    }
}

// =========================================================================
// Chunked parallel complex scan (input: packed ub, output: bf16 split xc)
// =========================================================================
__global__ void scan_local_kernel(const float* __restrict__ Are,
                                  const float* __restrict__ Aim,
                                  const float* __restrict__ ub,
                                  float* __restrict__ xc,
                                  float* __restrict__ endr,
                                  float* __restrict__ endi) {
    int t = blockIdx.x * blockDim.x + threadIdx.x;
    int s = t % S_;
    int c = (t / S_) % CH_;
    int b = t / (S_ * CH_);
    float ar = Are[s], ai = Aim[s];
    float xr = 0.f, xi = 0.f;
    int tok0 = b * L_ + c * CL_;
    size_t base = (size_t)tok0 * S2_ + s;
    for (int j = 0; j < CL_; j++) {
        size_t o = base + (size_t)j * S2_;
        float ur = ub[o], ui = ub[o + S_];
        float nr = fmaf(ar, xr, fmaf(-ai, xi, ur));
        float ni = fmaf(ar, xi, fmaf(ai, xr, ui));
        xr = nr; xi = ni;
        xc[o] = xr; xc[o + S_] = xi;
    }
    endr[(b * CH_ + c) * S_ + s] = xr;
    endi[(b * CH_ + c) * S_ + s] = xi;
}

__global__ void scan_combine_kernel(const float* __restrict__ Are,
                                    const float* __restrict__ Aim,
                                    const float* __restrict__ endr,
                                    const float* __restrict__ endi,
                                    float* __restrict__ incr,
                                    float* __restrict__ inci) {
    int t = blockIdx.x * blockDim.x + threadIdx.x;
    if (t >= B_ * S_) return;
    int s = t % S_;
    int b = t / S_;
    float ar = Are[s], ai = Aim[s];
    float pr = 1.f, pi = 0.f;
    for (int j = 0; j < CL_; j++) {
        float nr = pr * ar - pi * ai;
        float ni = pr * ai + pi * ar;
        pr = nr; pi = ni;
    }
    float cr = 0.f, ci = 0.f;
    for (int c = 0; c < CH_; c++) {
        int idx = (b * CH_ + c) * S_ + s;
        incr[idx] = cr; inci[idx] = ci;
        float er = endr[idx], ei = endi[idx];
        float nr = fmaf(pr, cr, fmaf(-pi, ci, er));
        float ni = fmaf(pr, ci, fmaf(pi, cr, ei));
        cr = nr; ci = ni;
    }
}

__global__ void scan_fix_kernel(const float* __restrict__ Are,
                                const float* __restrict__ Aim,
                                const float* __restrict__ incr,
                                const float* __restrict__ inci,
                                const float* __restrict__ xc,
                                __nv_bfloat16* __restrict__ xchi,
                                __nv_bfloat16* __restrict__ xclo) {
    int t = blockIdx.x * blockDim.x + threadIdx.x;
    int s = t % S_;
    int c = (t / S_) % CH_;
    int b = t / (S_ * CH_);
    int cidx = (b * CH_ + c) * S_ + s;
    float x0r = incr[cidx], x0i = inci[cidx];
    float ar = Are[s], ai = Aim[s];
    float pr = ar, pi = ai;
    int tok0 = b * L_ + c * CL_;
    size_t base = (size_t)tok0 * S2_ + s;
    for (int j = 0; j < CL_; j++) {
        size_t o = base + (size_t)j * S2_;
        float vr = xc[o]      + (pr * x0r - pi * x0i);
        float vi = xc[o + S_] + (pr * x0i + pi * x0r);
        __nv_bfloat16 hr = __float2bfloat16(vr);
        xchi[o] = hr;
        xclo[o] = __float2bfloat16(vr - __bfloat162float(hr));
        __nv_bfloat16 hi2 = __float2bfloat16(vi);
        xchi[o + S_] = hi2;
        xclo[o + S_] = __float2bfloat16(vi - __bfloat162float(hi2));
        float nr = pr * ar - pi * ai;
        float ni = pr * ai + pi * ar;
        pr = nr; pi = ni;
    }
}

// =========================================================================
// small converters
// =========================================================================
__global__ void ccat_kernel(const float* __restrict__ Cre,
                            const float* __restrict__ Cim,
                            __nv_bfloat16* __restrict__ hi,
                            __nv_bfloat16* __restrict__ lo) {
    int i = blockIdx.x * blockDim.x + threadIdx.x;
    int row = i >> 10;
    int d = i & 1023;
    float v = (row < S_) ? Cre[row * D_ + d] : -Cim[(row - S_) * D_ + d];
    __nv_bfloat16 h = __float2bfloat16(v);
    hi[i] = h;
    lo[i] = __float2bfloat16(v - __bfloat162float(h));
}

__global__ void bcat_kernel(const float* __restrict__ Bre,
                            const float* __restrict__ Bim,
                            __nv_bfloat16* __restrict__ hi,
                            __nv_bfloat16* __restrict__ lo) {
    int i = blockIdx.x * blockDim.x + threadIdx.x;   // D_*S2_
    int d = i >> 9;
    int c = i & 511;
    float v = (c < S_) ? Bre[d * S_ + c] : Bim[d * S_ + (c - S_)];
    __nv_bfloat16 h = __float2bfloat16(v);
    hi[i] = h;
    lo[i] = __float2bfloat16(v - __bfloat162float(h));
}

__global__ void wsplit_bias_kernel(const float* __restrict__ Hw,
                                   const float* __restrict__ Dp,
                                   const float* __restrict__ Hb,
                                   __nv_bfloat16* __restrict__ whi,
                                   __nv_bfloat16* __restrict__ wlo,
                                   float* __restrict__ gb) {
    int v = blockIdx.x * blockDim.x + threadIdx.x;
    if (v >= V_) return;
    float acc = 0.f;
    for (int d = 0; d < D_; d++) {
        size_t o = (size_t)d * V_ + v;
        float w = Hw[o];
        __nv_bfloat16 h = __float2bfloat16(w);
        whi[o] = h;
        wlo[o] = __float2bfloat16(w - __bfloat162float(h));
        acc = fmaf(Dp[d], w, acc);
    }
    gb[v] = acc + Hb[v];
}

// =========================================================================
// Split-bf16 HMMA GEMM. CTA tile 128x256, BK=32, 8 warps (2m x 4n, 64x64),
// 3-stage cp.async pipeline. 3-term: AhiBhi + AloBhi + AhiBlo.
// Epilogue: fp32 (+bias) OR bf16 hi/lo split.
// =========================================================================
#define GBM 128
#define GBN 256
#define GBK 32
#define A_STRIDE 80                     /* (32+8)*2B per A row */
#define B_STRIDE 528                    /* (256+8)*2B per B row */
#define A_SPLIT  (128*A_STRIDE)         /* 10240 */
#define A_TOT    (2*A_SPLIT)            /* 20480 */
#define B_SPLIT  (GBK*B_STRIDE)         /* 16896 */
#define STAGE_BYTES (A_TOT + 2*B_SPLIT) /* 54272 */
#define GSMEM (3*STAGE_BYTES)           /* 162816 */

__global__ __launch_bounds__(256, 1)
void mma_gemm(const __nv_bfloat16* __restrict__ Ahi,
              const __nv_bfloat16* __restrict__ Alo,
              const __nv_bfloat16* __restrict__ Bhi,
              const __nv_bfloat16* __restrict__ Blo,
              float* __restrict__ Cf,
              __nv_bfloat16* __restrict__ Chi,
              __nv_bfloat16* __restrict__ Clo,
              const float* __restrict__ bias,
              int Mdim, int Ndim, int Kdim) {
    extern __shared__ char smem[];
    uint32_t sbase = smem_to_u32(smem);
    const int tid = threadIdx.x;
    const int lane = tid & 31, wid = tid >> 5;
    const int wm = wid & 1, wn = wid >> 1;          // 2 x 4 warps
    const int brow = blockIdx.x * GBM;
    const int bcol = blockIdx.y * GBN;
    const int lda = Kdim, ldb = Ndim;
    const int niter = Kdim / GBK;

    float acc[4][8][4];
#pragma unroll
    for (int i = 0; i < 4; i++)
#pragma unroll
        for (int j = 0; j < 8; j++)
#pragma unroll
            for (int k = 0; k < 4; k++) acc[i][j][k] = 0.f;

    auto load_stage = [&](int kt, int st) {
        const int k0 = kt * GBK;
        uint32_t sa = sbase + st * STAGE_BYTES;
#pragma unroll
        for (int i = 0; i < 2; i++) {                // A: 512 16B chunks/split
            int c = tid + i * 256;
            int r = c >> 2, ch = c & 3;
            uint32_t dst = sa + r * A_STRIDE + ch * 16;
            size_t src = (size_t)(brow + r) * lda + k0 + ch * 8;
            cp_async16(dst,           Ahi + src);
            cp_async16(dst + A_SPLIT, Alo + src);
        }
#pragma unroll
        for (int i = 0; i < 4; i++) {                // B: 1024 16B chunks/split
            int c = tid + i * 256;
            int r = c >> 5, ch = c & 31;
            uint32_t dst = sa + A_TOT + r * B_STRIDE + ch * 16;
            size_t src = (size_t)(k0 + r) * ldb + bcol + ch * 8;
            cp_async16(dst,           Bhi + src);
            cp_async16(dst + B_SPLIT, Blo + src);
        }
    };

    load_stage(0, 0); CP_COMMIT();
    load_stage(1, 1); CP_COMMIT();

    for (int kt = 0; kt < niter; kt++) {
        if (kt + 2 < niter) {
            load_stage(kt + 2, (kt + 2) % 3);
            CP_COMMIT();
            CP_WAIT(2);
        } else if (kt + 2 == niter) {
            CP_WAIT(1);
        } else {
            CP_WAIT(0);
        }
        __syncthreads();

        uint32_t sa = sbase + (kt % 3) * STAGE_BYTES;
#pragma unroll
        for (int ks = 0; ks < 2; ks++) {
            uint32_t ah[4][4], al[4][4];
#pragma unroll
            for (int mf = 0; mf < 4; mf++) {
                uint32_t addr = sa + (wm * 64 + mf * 16 + (lane & 15)) * A_STRIDE
                              + ks * 32 + (lane >> 4) * 16;
                LDSM4(ah[mf][0], ah[mf][1], ah[mf][2], ah[mf][3], addr);
                LDSM4(al[mf][0], al[mf][1], al[mf][2], al[mf][3], addr + A_SPLIT);
            }
            uint32_t bh[8][2], bl[8][2];
#pragma unroll
            for (int g = 0; g < 4; g++) {
                uint32_t addr = sa + A_TOT + (ks * 16 + (lane & 15)) * B_STRIDE
                              + (wn * 64 + g * 16 + (lane >> 4) * 8) * 2;
                uint32_t r0, r1, r2, r3;
                LDSM4T(r0, r1, r2, r3, addr);
                bh[2 * g][0] = r0; bh[2 * g][1] = r1;
                bh[2 * g + 1][0] = r2; bh[2 * g + 1][1] = r3;
                LDSM4T(r0, r1, r2, r3, addr + B_SPLIT);
                bl[2 * g][0] = r0; bl[2 * g][1] = r1;
                bl[2 * g + 1][0] = r2; bl[2 * g + 1][1] = r3;
            }
#pragma unroll
            for (int mf = 0; mf < 4; mf++)
#pragma unroll
                for (int nf = 0; nf < 8; nf++) {
                    MMA_BF16(acc[mf][nf], ah[mf][0], ah[mf][1], ah[mf][2], ah[mf][3],
                             bh[nf][0], bh[nf][1]);
                    MMA_BF16(acc[mf][nf], al[mf][0], al[mf][1], al[mf][2], al[mf][3],
                             bh[nf][0], bh[nf][1]);
                    MMA_BF16(acc[mf][nf], ah[mf][0], ah[mf][1], ah[mf][2], ah[mf][3],
                             bl[nf][0], bl[nf][1]);
                }
        }
        __syncthreads();
    }

    if (Chi) {
        // bf16 hi/lo split epilogue
#pragma unroll
        for (int mf = 0; mf < 4; mf++) {
            int r0 = brow + wm * 64 + mf * 16 + (lane >> 2);
#pragma unroll
            for (int nf = 0; nf < 8; nf++) {
                int c0 = bcol + wn * 64 + nf * 8 + (lane & 3) * 2;
#pragma unroll
                for (int half = 0; half < 2; half++) {
                    float v0 = acc[mf][nf][2 * half];
                    float v1 = acc[mf][nf][2 * half + 1];
                    __nv_bfloat16 h0 = __float2bfloat16(v0);
                    __nv_bfloat16 h1 = __float2bfloat16(v1);
                    __nv_bfloat162 hv; hv.x = h0; hv.y = h1;
                    __nv_bfloat162 lv;
                    lv.x = __float2bfloat16(v0 - __bfloat162float(h0));
                    lv.y = __float2bfloat16(v1 - __bfloat162float(h1));
                    size_t off = (size_t)(r0 + 8 * half) * Ndim + c0;
                    *(__nv_bfloat162*)(Chi + off) = hv;
                    *(__nv_bfloat162*)(Clo + off) = lv;
                }
            }
        }
    } else {
#pragma unroll
        for (int mf = 0; mf < 4; mf++) {
            int r0 = brow + wm * 64 + mf * 16 + (lane >> 2);
#pragma unroll
            for (int nf = 0; nf < 8; nf++) {
                int c0 = bcol + wn * 64 + nf * 8 + (lane & 3) * 2;
                float b0 = 0.f, b1 = 0.f;
                if (bias) { b0 = __ldg(bias + c0); b1 = __ldg(bias + c0 + 1); }
                float2 v0 = make_float2(acc[mf][nf][0] + b0, acc[mf][nf][1] + b1);
                float2 v1 = make_float2(acc[mf][nf][2] + b0, acc[mf][nf][3] + b1);
                *(float2*)(Cf + (size_t)r0 * Ndim + c0)       = v0;
                *(float2*)(Cf + (size_t)(r0 + 8) * Ndim + c0) = v1;
            }
        }
    }
}

// =========================================================================
extern "C" void kernel_launch(void* const* d_in, const int* in_sizes, int n_in,
                              void* d_out, int out_size) {
    const int*   ids = (const int*)  d_in[0];
    const float* emb = (const float*)d_in[1];
    const float* w1  = (const float*)d_in[2];
    const float* w2  = (const float*)d_in[3];
    const float* Are = (const float*)d_in[4];
    const float* Aim = (const float*)d_in[5];
    const float* Bre = (const float*)d_in[6];
    const float* Bim = (const float*)d_in[7];
    const float* Cre = (const float*)d_in[8];
    const float* Cim = (const float*)d_in[9];
    const float* Dp  = (const float*)d_in[10];
    const float* Hw  = (const float*)d_in[11];
    const float* Hb  = (const float*)d_in[12];
    float* out = (float*)d_out;

    float *ub, *xc, *endr, *endi, *incr, *inci, *gb;
    __nv_bfloat16 *uhi, *ulo, *bchi, *bclo, *xchi, *xclo;
    __nv_bfloat16 *cchi, *cclo, *whi, *wlo, *Ghi, *Glo;
    cudaGetSymbolAddress((void**)&ub,   g_ub);
    cudaGetSymbolAddress((void**)&xc,   g_xc);
    cudaGetSymbolAddress((void**)&endr, g_endr);
    cudaGetSymbolAddress((void**)&endi, g_endi);
    cudaGetSymbolAddress((void**)&incr, g_incr);
    cudaGetSymbolAddress((void**)&inci, g_inci);
    cudaGetSymbolAddress((void**)&uhi,  g_uhi);
    cudaGetSymbolAddress((void**)&ulo,  g_ulo);
    cudaGetSymbolAddress((void**)&bchi, g_bchi);
    cudaGetSymbolAddress((void**)&bclo, g_bclo);
    cudaGetSymbolAddress((void**)&xchi, g_xchi);
    cudaGetSymbolAddress((void**)&xclo, g_xclo);
    cudaGetSymbolAddress((void**)&cchi, g_cchi);
    cudaGetSymbolAddress((void**)&cclo, g_cclo);
    cudaGetSymbolAddress((void**)&whi,  g_whi);
    cudaGetSymbolAddress((void**)&wlo,  g_wlo);
    cudaGetSymbolAddress((void**)&Ghi,  g_Ghi);
    cudaGetSymbolAddress((void**)&Glo,  g_Glo);
    cudaGetSymbolAddress((void**)&gb,   g_gb);

    cudaFuncSetAttribute(mma_gemm,
                         cudaFuncAttributeMaxDynamicSharedMemorySize, GSMEM);

    // ---- weight prep ----
    wsplit_bias_kernel<<<(V_ + 255) / 256, 256>>>(Hw, Dp, Hb, whi, wlo, gb);
    ccat_kernel<<<(S2_ * D_) / 256, 256>>>(Cre, Cim, cchi, cclo);
    bcat_kernel<<<(D_ * S2_) / 256, 256>>>(Bre, Bim, bchi, bclo);

    // G = Ccat @ Hw  [512, 32000], bf16 hi/lo epilogue
    mma_gemm<<<dim3(S2_ / GBM, V_ / GBN), 256, GSMEM>>>(
        cchi, cclo, whi, wlo, nullptr, Ghi, Glo, nullptr, S2_, V_, D_);

    // ---- activation chain ----
    embed_norm_kernel<<<M_, 256>>>(ids, emb, w1, w2, uhi, ulo);

    // uB = u @ Bcat  [4096, 512] fp32, packed [re|im]
    mma_gemm<<<dim3(M_ / GBM, S2_ / GBN), 256, GSMEM>>>(
        uhi, ulo, bchi, bclo, ub, nullptr, nullptr, nullptr, M_, S2_, D_);

    // parallel complex scan -> xchi/xclo
    scan_local_kernel<<<(B_ * CH_ * S_) / 256, 256>>>(Are, Aim, ub, xc, endr, endi);
    scan_combine_kernel<<<(B_ * S_ + 255) / 256, 256>>>(Are, Aim, endr, endi, incr, inci);
    scan_fix_kernel<<<(B_ * CH_ * S_) / 256, 256>>>(Are, Aim, incr, inci, xc, xchi, xclo);

    // logits = xc @ G + gb  [4096, 32000]
    mma_gemm<<<dim3(M_ / GBM, V_ / GBN), 256, GSMEM>>>(
        xchi, xclo, Ghi, Glo, out, nullptr, nullptr, gb, M_, V_, S2_);
}